// round 5
// baseline (speedup 1.0000x reference)
#include <cuda_runtime.h>
#include <cuda_fp16.h>
#include <stdint.h>

#define MAXN 50000
#define MAXE 800000
#define XD 32
#define HD 96
#define OD 64
#define NBLK 592
#define NTHR 256
#define PQB  296
#define NB256 ((MAXN + 255) / 256)

// ---- device scratch ----
__device__ float   g_A[XD * HD];
__device__ float   g_B[XD * HD];
__device__ float   g_c[HD];
__device__ float   g_p[MAXN * HD];
__device__ __half2 g_qh[MAXN * (HD / 2)];
__device__ int     g_deg[MAXN];
__device__ int     g_off[MAXN + 1];
__device__ int     g_rank[MAXE];
__device__ int     g_srcs[MAXE];
__device__ int     g_bsum[NB256];
__device__ int     g_is64;

// ---- grid barrier state ----
__device__ int          g_bar_count = 0;
__device__ volatile int g_bar_gen = 0;

__device__ __forceinline__ void grid_sync() {
    __syncthreads();
    if (threadIdx.x == 0) {
        __threadfence();
        int gen = g_bar_gen;
        if (atomicAdd(&g_bar_count, 1) == NBLK - 1) {
            g_bar_count = 0;
            __threadfence();
            g_bar_gen = gen + 1;
        } else {
            while (g_bar_gen == gen) { __nanosleep(64); }
        }
        __threadfence();
    }
    __syncthreads();
}

__device__ __forceinline__ int load_idx(const void* ei, int i) {
    if (g_is64) return (int)((const long long*)ei)[i];
    return ((const int*)ei)[i];
}

__device__ __forceinline__ int warp_reduce(int v) {
#pragma unroll
    for (int o = 16; o > 0; o >>= 1) v += __shfl_down_sync(0xffffffffu, v, o);
    return v;
}

__global__ void __launch_bounds__(NTHR, 4)
fused_kernel(const float* __restrict__ x, const float* __restrict__ scalars,
             const float* __restrict__ W1, const float* __restrict__ b1,
             const float* __restrict__ W2, const float* __restrict__ b2,
             const void* __restrict__ ei, float* __restrict__ out,
             int n, int e) {
    __shared__ union {
        struct { float sA[XD * HD]; float sB[XD * HD]; float sc[HD]; float xs[5][XD]; } pq;
        struct { float sW2[HD * OD]; float sb2[OD]; float zbuf[8][HD]; } eo;
    } sm;
    __shared__ int s_any;
    __shared__ int s_wsum[8];
    __shared__ int s_wpre[8];
    __shared__ int s_base;

    const int tid = threadIdx.x;
    const int bid = blockIdx.x;
    const int lane = tid & 31;
    const int wid = tid >> 5;
    const int nb = (n + 255) / 256;

    // ================= P0: zero deg, detect dtype, prep A/B/c =================
    for (int i = bid * NTHR + tid; i < n; i += NBLK * NTHR) g_deg[i] = 0;
    if (bid == 0) {
        if (tid == 0) s_any = 0;
        __syncthreads();
        const int* ei32 = (const int*)ei;
        for (int k = tid; k < 1024; k += NTHR)
            if (ei32[2 * k + 1] != 0) s_any = 1;
        __syncthreads();
        if (tid == 0) g_is64 = (s_any == 0) ? 1 : 0;
    }
    if (bid == 1 && tid < HD) {
        int j = tid;
        float c = b1[j];
#pragma unroll
        for (int s = 0; s < 16; s++) c += scalars[s] * W1[(32 + s) * HD + j];
        g_c[j] = c;
#pragma unroll
        for (int r = 0; r < XD; r++) {
            float wB = W1[(48 + r) * HD + j];
            g_A[r * HD + j] = W1[r * HD + j] - wB;
            g_B[r * HD + j] = wB;
        }
    }
    grid_sync();

    // ================= P1: pq (blocks < PQB) || hist (rest) =================
    if (bid < PQB) {
        for (int i = tid; i < XD * HD; i += NTHR) {
            sm.pq.sA[i] = g_A[i];
            sm.pq.sB[i] = g_B[i];
        }
        if (tid < HD) sm.pq.sc[tid] = g_c[tid];
        __syncthreads();
        int grp = tid / 48;    // 0..4 active (5 nodes/block/round), 5 = idle
        int t = tid % 48;
        for (int g = bid; g * 5 < n; g += PQB) {
            int node = g * 5 + grp;
            bool valid = (grp < 5) && (node < n);
            __syncthreads();
            if (valid && t < XD) sm.pq.xs[grp][t] = x[node * XD + t];
            __syncthreads();
            if (valid) {
                float p0 = sm.pq.sc[2 * t], p1 = sm.pq.sc[2 * t + 1];
                float q0 = 0.f, q1 = 0.f;
#pragma unroll
                for (int r = 0; r < XD; r++) {
                    float xv = sm.pq.xs[grp][r];
                    p0 = fmaf(xv, sm.pq.sA[r * HD + 2 * t], p0);
                    p1 = fmaf(xv, sm.pq.sA[r * HD + 2 * t + 1], p1);
                    q0 = fmaf(xv, sm.pq.sB[r * HD + 2 * t], q0);
                    q1 = fmaf(xv, sm.pq.sB[r * HD + 2 * t + 1], q1);
                }
                ((float2*)g_p)[(size_t)node * 48 + t] = make_float2(p0, p1);
                g_qh[(size_t)node * 48 + t] = __floats2half2_rn(q0, q1);
            }
        }
    } else {
        const int hb = bid - PQB;
        for (int i = hb * NTHR + tid; i < e; i += (NBLK - PQB) * NTHR) {
            int dst = load_idx(ei, e + i);
            g_rank[i] = atomicAdd(&g_deg[dst], 1);
        }
    }
    grid_sync();

    // ================= P2a: all blocks stage W2; scan blocks do partials =====
    for (int i = tid; i < HD * OD; i += NTHR) sm.eo.sW2[i] = W2[i];
    if (tid < OD) sm.eo.sb2[tid] = b2[tid];
    for (int b = bid; b < nb; b += NBLK) {
        int i = b * 256 + tid;
        int v = (i < n) ? g_deg[i] : 0;
        int s = warp_reduce(v);
        if (lane == 0) s_wsum[wid] = s;
        __syncthreads();
        if (tid < 8) {
            int t = s_wsum[tid];
#pragma unroll
            for (int o = 4; o > 0; o >>= 1) t += __shfl_down_sync(0xffu, t, o);
            if (tid == 0) g_bsum[b] = t;
        }
        __syncthreads();
    }
    grid_sync();

    // ================= P2b: offsets =================
    for (int b = bid; b < nb; b += NBLK) {
        if (tid < 32) {
            int s = 0;
            for (int k = tid; k < b; k += 32) s += g_bsum[k];
            s = warp_reduce(s);
            if (tid == 0) s_base = s;
        }
        int i = b * 256 + tid;
        int v = (i < n) ? g_deg[i] : 0;
        int incl = v;
#pragma unroll
        for (int o = 1; o < 32; o <<= 1) {
            int t = __shfl_up_sync(0xffffffffu, incl, o);
            if (lane >= o) incl += t;
        }
        if (lane == 31) s_wpre[wid] = incl;
        __syncthreads();
        if (tid == 0) {
            int run = 0;
#pragma unroll
            for (int k = 0; k < 8; k++) { int t = s_wpre[k]; s_wpre[k] = run; run += t; }
        }
        __syncthreads();
        if (i < n) {
            int excl = s_base + s_wpre[wid] + incl - v;
            g_off[i] = excl;
            if (i == n - 1) g_off[n] = excl + v;
        }
        __syncthreads();
    }
    grid_sync();

    // ================= P3: deterministic scatter =================
    for (int i = bid * NTHR + tid; i < e; i += NBLK * NTHR) {
        int src = load_idx(ei, i);
        int dst = load_idx(ei, e + i);
        g_srcs[g_off[dst] + g_rank[i]] = src;
    }
    grid_sync();

    // ================= P4: edge accumulation + output GEMM =================
    for (int node = bid * 8 + wid; node < n; node += NBLK * 8) {
        int off0 = __ldg(&g_off[node]);
        int off1 = __ldg(&g_off[node + 1]);
        const float2* pp2 = (const float2*)g_p + (size_t)node * 48;
        float2 ppa = pp2[lane];
        float2 ppb = make_float2(0.f, 0.f);
        if (lane < 16) ppb = pp2[32 + lane];
        float z0x = 0.f, z0y = 0.f, z1x = 0.f, z1y = 0.f;

        for (int base = off0; base < off1; base += 32) {
            int cnt = min(32, off1 - base);
            int sreg = (lane < cnt) ? __ldg(&g_srcs[base + lane]) : 0;
            int k = 0;
            for (; k + 3 < cnt; k += 4) {
                int s0 = __shfl_sync(0xffffffffu, sreg, k);
                int s1 = __shfl_sync(0xffffffffu, sreg, k + 1);
                int s2 = __shfl_sync(0xffffffffu, sreg, k + 2);
                int s3 = __shfl_sync(0xffffffffu, sreg, k + 3);
                const __half2* q0 = g_qh + (size_t)s0 * 48;
                const __half2* q1 = g_qh + (size_t)s1 * 48;
                const __half2* q2 = g_qh + (size_t)s2 * 48;
                const __half2* q3 = g_qh + (size_t)s3 * 48;
                __half2 a0 = q0[lane], a1 = q1[lane], a2 = q2[lane], a3 = q3[lane];
                __half2 zero = __float2half2_rn(0.f);
                __half2 b0 = zero, b1h = zero, b2h = zero, b3 = zero;
                if (lane < 16) {
                    b0 = q0[32 + lane]; b1h = q1[32 + lane];
                    b2h = q2[32 + lane]; b3 = q3[32 + lane];
                }
                float2 f0 = __half22float2(a0), f1 = __half22float2(a1);
                float2 f2 = __half22float2(a2), f3 = __half22float2(a3);
                z0x += fmaxf(ppa.x + f0.x, 0.f) + fmaxf(ppa.x + f1.x, 0.f)
                     + fmaxf(ppa.x + f2.x, 0.f) + fmaxf(ppa.x + f3.x, 0.f);
                z0y += fmaxf(ppa.y + f0.y, 0.f) + fmaxf(ppa.y + f1.y, 0.f)
                     + fmaxf(ppa.y + f2.y, 0.f) + fmaxf(ppa.y + f3.y, 0.f);
                if (lane < 16) {
                    float2 g0 = __half22float2(b0), g1 = __half22float2(b1h);
                    float2 g2 = __half22float2(b2h), g3 = __half22float2(b3);
                    z1x += fmaxf(ppb.x + g0.x, 0.f) + fmaxf(ppb.x + g1.x, 0.f)
                         + fmaxf(ppb.x + g2.x, 0.f) + fmaxf(ppb.x + g3.x, 0.f);
                    z1y += fmaxf(ppb.y + g0.y, 0.f) + fmaxf(ppb.y + g1.y, 0.f)
                         + fmaxf(ppb.y + g2.y, 0.f) + fmaxf(ppb.y + g3.y, 0.f);
                }
            }
            for (; k < cnt; k++) {
                int s0 = __shfl_sync(0xffffffffu, sreg, k);
                const __half2* q0 = g_qh + (size_t)s0 * 48;
                float2 f0 = __half22float2(q0[lane]);
                z0x += fmaxf(ppa.x + f0.x, 0.f);
                z0y += fmaxf(ppa.y + f0.y, 0.f);
                if (lane < 16) {
                    float2 g0 = __half22float2(q0[32 + lane]);
                    z1x += fmaxf(ppb.x + g0.x, 0.f);
                    z1y += fmaxf(ppb.y + g0.y, 0.f);
                }
            }
        }
        sm.eo.zbuf[wid][2 * lane] = z0x;
        sm.eo.zbuf[wid][2 * lane + 1] = z0y;
        if (lane < 16) {
            sm.eo.zbuf[wid][64 + 2 * lane] = z1x;
            sm.eo.zbuf[wid][65 + 2 * lane] = z1y;
        }
        __syncwarp();

        int deg = off1 - off0;
        float a0 = (float)deg * sm.eo.sb2[lane];
        float a1 = (float)deg * sm.eo.sb2[lane + 32];
#pragma unroll
        for (int kk = 0; kk < HD; kk++) {
            float zv = sm.eo.zbuf[wid][kk];
            a0 = fmaf(zv, sm.eo.sW2[kk * OD + lane], a0);
            a1 = fmaf(zv, sm.eo.sW2[kk * OD + lane + 32], a1);
        }
        out[(size_t)node * OD + lane] = a0;
        out[(size_t)node * OD + lane + 32] = a1;
        __syncwarp();
    }
}

extern "C" void kernel_launch(void* const* d_in, const int* in_sizes, int n_in,
                              void* d_out, int out_size) {
    const float* x       = (const float*)d_in[0];
    const float* scalars = (const float*)d_in[1];
    const float* W1      = (const float*)d_in[2];
    const float* b1      = (const float*)d_in[3];
    const float* W2      = (const float*)d_in[4];
    const float* b2      = (const float*)d_in[5];
    const void*  ei      = d_in[6];
    float* out = (float*)d_out;

    int n = in_sizes[0] / XD;   // 50000
    int e = in_sizes[6] / 2;    // 800000

    fused_kernel<<<NBLK, NTHR>>>(x, scalars, W1, b1, W2, b2, ei, out, n, e);
}

// round 6
// speedup vs baseline: 1.2255x; 1.2255x over previous
#include <cuda_runtime.h>
#include <cuda_fp16.h>
#include <stdint.h>

#define MAXN 50000
#define MAXE 800000
#define XD 32
#define HD 96
#define OD 64
#define NB256 ((MAXN + 255) / 256)
#define PQBLK 391     // ceil(50000/128) pq blocks
#define HBLK  800     // hist blocks

// ---- device scratch ----
__device__ float   g_AT[HD * XD];          // transposed: AT[j][r]
__device__ float   g_BT[HD * XD];
__device__ float   g_c[HD];
__device__ float   g_p[MAXN * HD];
__device__ __half2 g_qh[MAXN * (HD / 2)];
__device__ int     g_deg[MAXN];
__device__ int     g_off[MAXN + 1];
__device__ int     g_rank[MAXE];
__device__ int     g_srcs[MAXE];
__device__ int     g_bsum[NB256];
__device__ int     g_is64;

__device__ __forceinline__ int load_idx(const void* ei, int i) {
    if (g_is64) return (int)((const long long*)ei)[i];
    return ((const int*)ei)[i];
}

__device__ __forceinline__ int warp_reduce(int v) {
#pragma unroll
    for (int o = 16; o > 0; o >>= 1) v += __shfl_down_sync(0xffffffffu, v, o);
    return v;
}

// ---- init: zero deg; block 0 detects dtype + builds AT/BT/c ----
__global__ void init_kernel(const float* __restrict__ W1,
                            const float* __restrict__ b1,
                            const float* __restrict__ scalars,
                            const int* __restrict__ ei32, int n) {
    int i = blockIdx.x * blockDim.x + threadIdx.x;
    if (i < n) g_deg[i] = 0;
    if (blockIdx.x == 0) {
        __shared__ int s_any;
        if (threadIdx.x == 0) s_any = 0;
        __syncthreads();
        for (int k = threadIdx.x; k < 1024; k += blockDim.x)
            if (ei32[2 * k + 1] != 0) s_any = 1;
        __syncthreads();
        if (threadIdx.x == 0) g_is64 = (s_any == 0) ? 1 : 0;
        int j = threadIdx.x;
        if (j < HD) {
            float c = b1[j];
#pragma unroll
            for (int s = 0; s < 16; s++) c += scalars[s] * W1[(32 + s) * HD + j];
            g_c[j] = c;
#pragma unroll
            for (int r = 0; r < XD; r++) {
                float wB = W1[(48 + r) * HD + j];
                g_AT[j * XD + r] = W1[r * HD + j] - wB;
                g_BT[j * XD + r] = wB;
            }
        }
    }
}

// ---- fused: pq (blocks < PQBLK, thread-per-node) + hist (rest) ----
__global__ void __launch_bounds__(128)
pqhist_kernel(const float* __restrict__ x, const void* __restrict__ ei,
              int n, int e) {
    __shared__ float sAT[HD][XD];
    __shared__ float sBT[HD][XD];
    __shared__ float sc[HD];
    __shared__ float xs[128][XD + 1];
    const int tid = threadIdx.x;

    if (blockIdx.x < PQBLK) {
        for (int i = tid; i < HD * XD; i += 128) {
            sAT[i >> 5][i & 31] = g_AT[i];
            sBT[i >> 5][i & 31] = g_BT[i];
        }
        if (tid < HD) sc[tid] = g_c[tid];

        const int base = blockIdx.x * 128;
        const int cnt = min(128, n - base);
        for (int i = tid; i < cnt * XD; i += 128)
            xs[i >> 5][i & 31] = x[base * XD + i];
        __syncthreads();

        const int node = base + tid;
        if (tid < cnt) {
            float xr[XD];
#pragma unroll
            for (int r = 0; r < XD; r++) xr[r] = xs[tid][r];

            for (int jc = 0; jc < 12; jc++) {
                float pa[8], qa[8];
#pragma unroll
                for (int u = 0; u < 8; u++) {
                    const int j = jc * 8 + u;
                    float ap = sc[j], aq = 0.f;
#pragma unroll
                    for (int r4 = 0; r4 < 8; r4++) {
                        float4 wa = *(const float4*)&sAT[j][r4 * 4];
                        float4 wb = *(const float4*)&sBT[j][r4 * 4];
                        ap = fmaf(xr[r4 * 4 + 0], wa.x, ap);
                        ap = fmaf(xr[r4 * 4 + 1], wa.y, ap);
                        ap = fmaf(xr[r4 * 4 + 2], wa.z, ap);
                        ap = fmaf(xr[r4 * 4 + 3], wa.w, ap);
                        aq = fmaf(xr[r4 * 4 + 0], wb.x, aq);
                        aq = fmaf(xr[r4 * 4 + 1], wb.y, aq);
                        aq = fmaf(xr[r4 * 4 + 2], wb.z, aq);
                        aq = fmaf(xr[r4 * 4 + 3], wb.w, aq);
                    }
                    pa[u] = ap;
                    qa[u] = aq;
                }
                float4* gp = (float4*)(g_p + (size_t)node * HD + jc * 8);
                gp[0] = make_float4(pa[0], pa[1], pa[2], pa[3]);
                gp[1] = make_float4(pa[4], pa[5], pa[6], pa[7]);
                __half2 h[4];
                h[0] = __floats2half2_rn(qa[0], qa[1]);
                h[1] = __floats2half2_rn(qa[2], qa[3]);
                h[2] = __floats2half2_rn(qa[4], qa[5]);
                h[3] = __floats2half2_rn(qa[6], qa[7]);
                ((uint4*)g_qh)[(size_t)node * 12 + jc] = *(uint4*)h;
            }
        }
    } else {
        const int hb = blockIdx.x - PQBLK;
        for (int i = hb * 128 + tid; i < e; i += HBLK * 128) {
            int dst = load_idx(ei, e + i);
            g_rank[i] = atomicAdd(&g_deg[dst], 1);
        }
    }
}

// ---- scanA: per-256-block sums ----
__global__ void scanA_kernel(int n) {
    __shared__ int wsum[8];
    int tid = threadIdx.x;
    int i = blockIdx.x * 256 + tid;
    int v = (i < n) ? g_deg[i] : 0;
    int s = warp_reduce(v);
    if ((tid & 31) == 0) wsum[tid >> 5] = s;
    __syncthreads();
    if (tid < 8) {
        int t = wsum[tid];
#pragma unroll
        for (int o = 4; o > 0; o >>= 1) t += __shfl_down_sync(0xffu, t, o);
        if (tid == 0) g_bsum[blockIdx.x] = t;
    }
}

// ---- scanB: per-block exclusive scan with inline bsum prefix ----
__global__ void scanB_kernel(int n) {
    __shared__ int warp_pre[8];
    __shared__ int sbase;
    int tid = threadIdx.x;
    int lane = tid & 31, wid = tid >> 5;
    if (tid < 32) {
        int s = 0;
        for (int k = tid; k < (int)blockIdx.x; k += 32) s += g_bsum[k];
        s = warp_reduce(s);
        if (tid == 0) sbase = s;
    }
    int i = blockIdx.x * 256 + tid;
    int v = (i < n) ? g_deg[i] : 0;
    int incl = v;
#pragma unroll
    for (int o = 1; o < 32; o <<= 1) {
        int t = __shfl_up_sync(0xffffffffu, incl, o);
        if (lane >= o) incl += t;
    }
    if (lane == 31) warp_pre[wid] = incl;
    __syncthreads();
    if (tid == 0) {
        int run = 0;
#pragma unroll
        for (int k = 0; k < 8; k++) { int t = warp_pre[k]; warp_pre[k] = run; run += t; }
    }
    __syncthreads();
    if (i < n) {
        int excl = sbase + warp_pre[wid] + incl - v;
        g_off[i] = excl;
        if (i == n - 1) g_off[n] = excl + v;
    }
}

// ---- deterministic scatter ----
__global__ void scatter_kernel(const void* __restrict__ ei, int e) {
    int i = blockIdx.x * blockDim.x + threadIdx.x;
    if (i >= e) return;
    int src = load_idx(ei, i);
    int dst = load_idx(ei, e + i);
    g_srcs[g_off[dst] + g_rank[i]] = src;
}

// ---- fused edge accumulation (fp16 q gathers, 4-edge unroll) + out GEMM ----
__global__ void edgeout_kernel(const float* __restrict__ W2,
                               const float* __restrict__ b2,
                               float* __restrict__ out, int n) {
    __shared__ float sW2[HD * OD];
    __shared__ float sb2[OD];
    __shared__ float zbuf[8][HD];
    int tid = threadIdx.x;
    for (int i = tid; i < HD * OD; i += 256) sW2[i] = W2[i];
    if (tid < OD) sb2[tid] = b2[tid];
    __syncthreads();

    int w = tid >> 5, lane = tid & 31;
    int node = blockIdx.x * 8 + w;
    if (node >= n) return;

    int off0 = __ldg(&g_off[node]);
    int off1 = __ldg(&g_off[node + 1]);
    const float2* pp2 = (const float2*)g_p + (size_t)node * 48;
    float2 ppa = pp2[lane];
    float2 ppb = make_float2(0.f, 0.f);
    if (lane < 16) ppb = pp2[32 + lane];
    float z0x = 0.f, z0y = 0.f, z1x = 0.f, z1y = 0.f;

    for (int base = off0; base < off1; base += 32) {
        int cnt = min(32, off1 - base);
        int sreg = (lane < cnt) ? __ldg(&g_srcs[base + lane]) : 0;
        int k = 0;
        for (; k + 3 < cnt; k += 4) {
            int s0 = __shfl_sync(0xffffffffu, sreg, k);
            int s1 = __shfl_sync(0xffffffffu, sreg, k + 1);
            int s2 = __shfl_sync(0xffffffffu, sreg, k + 2);
            int s3 = __shfl_sync(0xffffffffu, sreg, k + 3);
            const __half2* q0 = g_qh + (size_t)s0 * 48;
            const __half2* q1 = g_qh + (size_t)s1 * 48;
            const __half2* q2 = g_qh + (size_t)s2 * 48;
            const __half2* q3 = g_qh + (size_t)s3 * 48;
            __half2 a0 = q0[lane], a1 = q1[lane], a2 = q2[lane], a3 = q3[lane];
            __half2 zero = __float2half2_rn(0.f);
            __half2 b0 = zero, b1h = zero, b2h = zero, b3 = zero;
            if (lane < 16) {
                b0 = q0[32 + lane]; b1h = q1[32 + lane];
                b2h = q2[32 + lane]; b3 = q3[32 + lane];
            }
            float2 f0 = __half22float2(a0), f1 = __half22float2(a1);
            float2 f2 = __half22float2(a2), f3 = __half22float2(a3);
            z0x += fmaxf(ppa.x + f0.x, 0.f) + fmaxf(ppa.x + f1.x, 0.f)
                 + fmaxf(ppa.x + f2.x, 0.f) + fmaxf(ppa.x + f3.x, 0.f);
            z0y += fmaxf(ppa.y + f0.y, 0.f) + fmaxf(ppa.y + f1.y, 0.f)
                 + fmaxf(ppa.y + f2.y, 0.f) + fmaxf(ppa.y + f3.y, 0.f);
            if (lane < 16) {
                float2 g0 = __half22float2(b0), g1 = __half22float2(b1h);
                float2 g2 = __half22float2(b2h), g3 = __half22float2(b3);
                z1x += fmaxf(ppb.x + g0.x, 0.f) + fmaxf(ppb.x + g1.x, 0.f)
                     + fmaxf(ppb.x + g2.x, 0.f) + fmaxf(ppb.x + g3.x, 0.f);
                z1y += fmaxf(ppb.y + g0.y, 0.f) + fmaxf(ppb.y + g1.y, 0.f)
                     + fmaxf(ppb.y + g2.y, 0.f) + fmaxf(ppb.y + g3.y, 0.f);
            }
        }
        for (; k < cnt; k++) {
            int s0 = __shfl_sync(0xffffffffu, sreg, k);
            const __half2* q0 = g_qh + (size_t)s0 * 48;
            float2 f0 = __half22float2(q0[lane]);
            z0x += fmaxf(ppa.x + f0.x, 0.f);
            z0y += fmaxf(ppa.y + f0.y, 0.f);
            if (lane < 16) {
                float2 g0 = __half22float2(q0[32 + lane]);
                z1x += fmaxf(ppb.x + g0.x, 0.f);
                z1y += fmaxf(ppb.y + g0.y, 0.f);
            }
        }
    }
    zbuf[w][2 * lane] = z0x;
    zbuf[w][2 * lane + 1] = z0y;
    if (lane < 16) {
        zbuf[w][64 + 2 * lane] = z1x;
        zbuf[w][65 + 2 * lane] = z1y;
    }
    __syncwarp();

    int deg = off1 - off0;
    float a0 = (float)deg * sb2[lane];
    float a1 = (float)deg * sb2[lane + 32];
#pragma unroll
    for (int kk = 0; kk < HD; kk++) {
        float zv = zbuf[w][kk];
        a0 = fmaf(zv, sW2[kk * OD + lane], a0);
        a1 = fmaf(zv, sW2[kk * OD + lane + 32], a1);
    }
    out[(size_t)node * OD + lane] = a0;
    out[(size_t)node * OD + lane + 32] = a1;
}

extern "C" void kernel_launch(void* const* d_in, const int* in_sizes, int n_in,
                              void* d_out, int out_size) {
    const float* x       = (const float*)d_in[0];
    const float* scalars = (const float*)d_in[1];
    const float* W1      = (const float*)d_in[2];
    const float* b1      = (const float*)d_in[3];
    const float* W2      = (const float*)d_in[4];
    const float* b2      = (const float*)d_in[5];
    const void*  ei      = d_in[6];
    float* out = (float*)d_out;

    int n = in_sizes[0] / XD;   // 50000
    int e = in_sizes[6] / 2;    // 800000
    int nb = (n + 255) / 256;

    init_kernel<<<nb, 256>>>(W1, b1, scalars, (const int*)ei, n);
    pqhist_kernel<<<PQBLK + HBLK, 128>>>(x, ei, n, e);
    scanA_kernel<<<nb, 256>>>(n);
    scanB_kernel<<<nb, 256>>>(n);
    scatter_kernel<<<(e + 255) / 256, 256>>>(ei, e);
    edgeout_kernel<<<(n + 7) / 8, 256>>>(W2, b2, out, n);
}